// round 5
// baseline (speedup 1.0000x reference)
#include <cuda_runtime.h>
#include <cstdint>

#define SQ 1024
#define HD 64
#define TQ 64          // query rows per CTA
#define CK 32          // key cols per chunk
#define NCH (SQ / CK)  // 32
#define NTHREADS 256

// ---- smem layout (floats) ----
// Qp: 4 tig-planes, each 64 rows x pitch 20 (16 used), plane stride 1288 (=8 mod 32, 16B-mult)
#define QPLANE 1288
#define QROWP 20
#define OFF_QP 0                     // 4*1288 = 5152
// K/V double buffer: per buf K[64][40] (2560) + V[32][72] (2304) = 4864
#define KP 40
#define VP 72
#define OFF_KV 5152
#define KVBUF 4864
#define VOFF 2560
#define OFF_RAWQ (OFF_KV + KVBUF)    // raw Q staged flat into buf1 (4096 <= 4864)
// E tile (single buffer): 64 x 36
#define ESP 36
#define OFF_ES (OFF_KV + 2*KVBUF)    // 14880, size 2304
#define OFF_RS (OFF_ES + 2304)       // 17184, 128
#define OFF_INV (OFF_RS + 128)       // 17312, 64
#define SMEM_FLOATS (OFF_INV + 64)   // 17376 floats = 69504 B

__device__ __forceinline__ unsigned f2tf32(float v) {
    unsigned r;
    asm("cvt.rna.tf32.f32 %0, %1;" : "=r"(r) : "f"(v));
    return r;
}
__device__ __forceinline__ float tf32f(float v) { return __uint_as_float(f2tf32(v)); }

__device__ __forceinline__ void mma16x8x8(float* c, const unsigned* a, const unsigned* b) {
    asm volatile(
        "mma.sync.aligned.m16n8k8.row.col.f32.tf32.tf32.f32 "
        "{%0,%1,%2,%3}, {%4,%5,%6,%7}, {%8,%9}, {%0,%1,%2,%3};\n"
        : "+f"(c[0]), "+f"(c[1]), "+f"(c[2]), "+f"(c[3])
        : "r"(a[0]), "r"(a[1]), "r"(a[2]), "r"(a[3]),
          "r"(b[0]), "r"(b[1]));
}

__device__ __forceinline__ void cp16(uint32_t dst, const void* src) {
    asm volatile("cp.async.cg.shared.global [%0], [%1], 16;" :: "r"(dst), "l"(src));
}
__device__ __forceinline__ void cp_commit() {
    asm volatile("cp.async.commit_group;" ::: "memory");
}
template<int N> __device__ __forceinline__ void cp_wait() {
    asm volatile("cp.async.wait_group %0;" :: "n"(N) : "memory");
}

__global__ __launch_bounds__(NTHREADS, 3)
void attn_k5_kernel(const float* __restrict__ q, const float* __restrict__ k,
                    const float* __restrict__ v, const float* __restrict__ prev,
                    const float* __restrict__ mask, const float* __restrict__ scale_p,
                    float* __restrict__ out, float* __restrict__ wts,
                    float* __restrict__ scr)
{
    extern __shared__ float smem[];
    const uint32_t sbase = (uint32_t)__cvta_generic_to_shared(smem);
    float* Qp = smem + OFF_QP;
    float* Es = smem + OFF_ES;
    float* rowsum = smem + OFF_RS;
    float* invs = smem + OFF_INV;

    const int bh  = blockIdx.y;
    const int q0  = blockIdx.x * TQ;
    const int tid = threadIdx.x;
    const int wid = tid >> 5;
    const int lane = tid & 31;
    const int gID = lane >> 2;       // 0..7
    const int tig = lane & 3;        // 0..3
    const int wm  = wid & 3;         // 4-way M split (16 rows)
    const int wn  = wid >> 2;        // 2-way N split (16 cols of CK=32)
    const int r0  = wm * 16 + gID;
    const int r1  = r0 + 8;
    const int gr0 = q0 + r0;
    const int gr1 = q0 + r1;

    const float scale = __ldg(scale_p);

    const float* qh = q    + (size_t)bh * SQ * HD;
    const float* kh = k    + (size_t)bh * HD * SQ;   // [D][S]
    const float* vh = v    + (size_t)bh * SQ * HD;
    const float* ph = prev + (size_t)bh * SQ * SQ;
    float* outh = out + (size_t)bh * SQ * HD;
    float* wh   = wts + (size_t)bh * SQ * SQ;
    float* shh  = scr + (size_t)bh * SQ * SQ;

    // ---- stage K,V for chunk ch into buffer buf (4 cp16 per thread) ----
    auto stage_chunk = [&](int ch, int buf) {
        const int s0 = ch * CK;
        const int kvb = OFF_KV + buf * KVBUF;
        #pragma unroll
        for (int j = 0; j < 2; j++) {          // K [64 d][32 s]
            int i = tid + j * NTHREADS;
            int r = i >> 3, c = (i & 7) << 2;
            cp16(sbase + (uint32_t)(kvb + r * KP + c) * 4,
                 kh + (size_t)r * SQ + s0 + c);
        }
        #pragma unroll
        for (int j = 0; j < 2; j++) {          // V [32 s][64 d]
            int i = tid + j * NTHREADS;
            int r = i >> 4, c = (i & 15) << 2;
            cp16(sbase + (uint32_t)(kvb + VOFF + r * VP + c) * 4,
                 vh + (size_t)(s0 + r) * HD + c);
        }
    };

    // ---- prologue: raw Q -> buf1 flat, chunk0 -> buf0 ----
    #pragma unroll
    for (int j = 0; j < 4; j++) {
        int i = tid + j * NTHREADS;            // float4 index over 64x64 Q
        cp16(sbase + (uint32_t)(OFF_RAWQ + i * 4) * 4,
             qh + (size_t)(q0 + (i >> 4)) * HD + ((i & 15) << 2));
    }
    cp_commit();
    stage_chunk(0, 0);
    cp_commit();

    // prev prefetch (chunk 0) into registers
    float2 nx0[2], nx1[2];
    #pragma unroll
    for (int n = 0; n < 2; n++) {
        const int col = wn * 16 + n * 8 + tig * 2;
        nx0[n] = *(const float2*)(ph + (size_t)gr0 * SQ + col);
        nx1[n] = *(const float2*)(ph + (size_t)gr1 * SQ + col);
    }

    cp_wait<1>();          // raw Q landed
    __syncthreads();

    // ---- one-time: permute + tf32-convert Q into tig-planes ----
    {
        const int r = tid >> 2;
        const int db = (tid & 3) * 16;
        const float* raw = smem + OFF_RAWQ + r * HD + db;
        #pragma unroll
        for (int j4 = 0; j4 < 4; j4++) {
            float4 t = *(const float4*)(raw + j4 * 4);
            #pragma unroll
            for (int e = 0; e < 4; e++) {
                int d = db + j4 * 4 + e;
                float val = tf32f((&t.x)[e]);
                Qp[(d & 3) * QPLANE + r * QROWP + (d >> 3) + 8 * ((d >> 2) & 1)] = val;
            }
        }
    }
    __syncthreads();       // permute consumed raw Q; buf1 reusable

    float oacc[4][4];
    #pragma unroll
    for (int n = 0; n < 4; n++) {
        oacc[n][0] = 0.f; oacc[n][1] = 0.f; oacc[n][2] = 0.f; oacc[n][3] = 0.f;
    }
    float ls0 = 0.f, ls1 = 0.f;

    const uint32_t qb0 = tig * QPLANE + r0 * QROWP;
    const uint32_t qb1 = tig * QPLANE + r1 * QROWP;

    for (int ch = 0; ch < NCH; ch++) {
        const int buf = ch & 1;
        const int s0 = ch * CK;
        float* Ks = smem + OFF_KV + buf * KVBUF;
        float* Vs = Ks + VOFF;

        float2 pv0[2], pv1[2];
        pv0[0] = nx0[0]; pv0[1] = nx0[1];
        pv1[0] = nx1[0]; pv1[1] = nx1[1];

        if (ch + 1 < NCH) {
            stage_chunk(ch + 1, buf ^ 1);
            cp_commit();
            const int sn = (ch + 1) * CK;
            #pragma unroll
            for (int n = 0; n < 2; n++) {
                const int col = sn + wn * 16 + n * 8 + tig * 2;
                nx0[n] = *(const float2*)(ph + (size_t)gr0 * SQ + col);
                nx1[n] = *(const float2*)(ph + (size_t)gr1 * SQ + col);
            }
            cp_wait<1>();
        } else {
            cp_wait<0>();
        }
        __syncthreads();

        // ---- in-place tf32 conversion of K+V buffer (4864 floats = 1216 f4) ----
        {
            float4* p = (float4*)(smem + OFF_KV + buf * KVBUF);
            #pragma unroll
            for (int j = 0; j < 5; j++) {
                int idx = tid + j * NTHREADS;
                if (idx < KVBUF / 4) {
                    float4 t = p[idx];
                    t.x = tf32f(t.x); t.y = tf32f(t.y);
                    t.z = tf32f(t.z); t.w = tf32f(t.w);
                    p[idx] = t;
                }
            }
        }
        __syncthreads();

        // ---- mma1: S = Q @ K (per-warp 16x16), A from vectorized planes ----
        float acc[2][4];
        #pragma unroll
        for (int n = 0; n < 2; n++) {
            acc[n][0] = 0.f; acc[n][1] = 0.f; acc[n][2] = 0.f; acc[n][3] = 0.f;
        }
        #pragma unroll
        for (int half = 0; half < 2; half++) {
            float4 qlo0 = *(const float4*)(Qp + qb0 + half * 4);
            float4 qhi0 = *(const float4*)(Qp + qb0 + 8 + half * 4);
            float4 qlo1 = *(const float4*)(Qp + qb1 + half * 4);
            float4 qhi1 = *(const float4*)(Qp + qb1 + 8 + half * 4);
            #pragma unroll
            for (int k2 = 0; k2 < 4; k2++) {
                const int d0 = (half * 4 + k2) * 8;
                unsigned a[4];
                a[0] = __float_as_uint((&qlo0.x)[k2]);
                a[1] = __float_as_uint((&qlo1.x)[k2]);
                a[2] = __float_as_uint((&qhi0.x)[k2]);
                a[3] = __float_as_uint((&qhi1.x)[k2]);
                #pragma unroll
                for (int n = 0; n < 2; n++) {
                    const int col = wn * 16 + n * 8 + gID;
                    unsigned b[2];
                    b[0] = __float_as_uint(Ks[(d0 + tig) * KP + col]);
                    b[1] = __float_as_uint(Ks[(d0 + tig + 4) * KP + col]);
                    mma16x8x8(acc[n], a, b);
                }
            }
        }

        // ---- epilogue: scores -> gmem, exp -> Es (pre-cvt), rowsums ----
        #pragma unroll
        for (int n = 0; n < 2; n++) {
            const int lc  = wn * 16 + n * 8 + tig * 2;
            const int col = s0 + lc;
            float2 mk0 = *(const float2*)(mask + (size_t)gr0 * SQ + col);
            float2 mk1 = *(const float2*)(mask + (size_t)gr1 * SQ + col);
            float s00 = acc[n][0] * mk0.x * scale + pv0[n].x;
            float s01 = acc[n][1] * mk0.y * scale + pv0[n].y;
            float s10 = acc[n][2] * mk1.x * scale + pv1[n].x;
            float s11 = acc[n][3] * mk1.y * scale + pv1[n].y;
            *(float2*)(shh + (size_t)gr0 * SQ + col) = make_float2(s00, s01);
            *(float2*)(shh + (size_t)gr1 * SQ + col) = make_float2(s10, s11);
            float e00 = __expf(s00), e01 = __expf(s01);
            float e10 = __expf(s10), e11 = __expf(s11);
            ls0 += e00 + e01;
            ls1 += e10 + e11;
            *(float2*)(Es + r0 * ESP + lc) = make_float2(tf32f(e00), tf32f(e01));
            *(float2*)(Es + r1 * ESP + lc) = make_float2(tf32f(e10), tf32f(e11));
        }
        __syncthreads();   // Es complete (cross-warp A-fragments)

        // ---- mma2: out_unnorm += E @ V (per-warp 16x32) ----
        #pragma unroll
        for (int kk = 0; kk < 4; kk++) {
            const int k0 = kk * 8;
            unsigned a[4];
            a[0] = __float_as_uint(Es[r0 * ESP + k0 + tig]);
            a[1] = __float_as_uint(Es[r1 * ESP + k0 + tig]);
            a[2] = __float_as_uint(Es[r0 * ESP + k0 + tig + 4]);
            a[3] = __float_as_uint(Es[r1 * ESP + k0 + tig + 4]);
            #pragma unroll
            for (int n = 0; n < 4; n++) {
                const int oc = wn * 32 + n * 8 + gID;
                unsigned b[2];
                b[0] = __float_as_uint(Vs[(k0 + tig) * VP + oc]);
                b[1] = __float_as_uint(Vs[(k0 + tig + 4) * VP + oc]);
                mma16x8x8(oacc[n], a, b);
            }
        }
        __syncthreads();   // buf consumed -> reusable for ch+2 staging; Es reusable
    }

    // ---- rowsums -> invs ----
    ls0 += __shfl_xor_sync(0xffffffffu, ls0, 1);
    ls0 += __shfl_xor_sync(0xffffffffu, ls0, 2);
    ls1 += __shfl_xor_sync(0xffffffffu, ls1, 1);
    ls1 += __shfl_xor_sync(0xffffffffu, ls1, 2);
    if (tig == 0) {
        rowsum[wn * 64 + r0] = ls0;
        rowsum[wn * 64 + r1] = ls1;
    }
    __syncthreads();
    if (tid < TQ) invs[tid] = 1.0f / (rowsum[tid] + rowsum[64 + tid]);
    __syncthreads();

    // ---- write output (normalized) ----
    {
        const float inv0 = invs[r0];
        const float inv1 = invs[r1];
        #pragma unroll
        for (int n = 0; n < 4; n++) {
            const int col = wn * 32 + n * 8 + tig * 2;
            *(float2*)(outh + (size_t)gr0 * HD + col) =
                make_float2(oacc[n][0] * inv0, oacc[n][1] * inv0);
            *(float2*)(outh + (size_t)gr1 * HD + col) =
                make_float2(oacc[n][2] * inv1, oacc[n][3] * inv1);
        }
    }

    // ---- weights tail: w = exp(score) * inv (streaming float4) ----
    #pragma unroll 4
    for (int i = tid; i < TQ * (SQ / 4); i += NTHREADS) {
        int r  = i >> 8;
        int c4 = (i & 255) << 2;
        const float iv = invs[r];
        float4 s = *(const float4*)(shh + (size_t)(q0 + r) * SQ + c4);
        float4 w;
        w.x = __expf(s.x) * iv; w.y = __expf(s.y) * iv;
        w.z = __expf(s.z) * iv; w.w = __expf(s.w) * iv;
        *(float4*)(wh + (size_t)(q0 + r) * SQ + c4) = w;
    }
}

extern "C" void kernel_launch(void* const* d_in, const int* in_sizes, int n_in,
                              void* d_out, int out_size) {
    const float* q     = (const float*)d_in[0];
    const float* k     = (const float*)d_in[1];
    const float* v     = (const float*)d_in[2];
    const float* prev  = (const float*)d_in[3];
    const float* mask  = (const float*)d_in[4];
    const float* scale = (const float*)d_in[5];

    float* out = (float*)d_out;
    float* wts = out + (size_t)8 * 16 * 1024 * 64;
    float* scr = wts + (size_t)8 * 16 * 1024 * 1024;

    const size_t smem_bytes = (size_t)SMEM_FLOATS * sizeof(float);   // 69504 B
    cudaFuncSetAttribute(attn_k5_kernel,
                         cudaFuncAttributeMaxDynamicSharedMemorySize, (int)smem_bytes);

    dim3 grid(SQ / TQ, 8 * 16);   // (16 q-tiles, 128 bh)
    attn_k5_kernel<<<grid, NTHREADS, smem_bytes>>>(q, k, v, prev, mask, scale,
                                                   out, wts, scr);
}